// round 1
// baseline (speedup 1.0000x reference)
#include <cuda_runtime.h>
#include <cuda_bf16.h>

// ---------------------------------------------------------------------------
// GPT block, fp32 SIMT baseline.
//   q = X@Wq^T ; k = X@Wk^T ; v = X@Wv^T          (NT gemm, M=16384,N=768,K=768)
//   S = q@k^T  per batch                           (NT gemm, M=N=4096,K=768, z=4)
//   softmax rows of S
//   newV = S@v per batch                           (NN gemm, M=4096,N=768,K=4096)
//   h = relu(newV@W1^T + b1)                       (NT, M=16384,N=3072,K=768)
//   out = h@W2^T + b2                              (NT, M=16384,N=768,K=3072)
// ---------------------------------------------------------------------------

#define BMT 128
#define BNT 128
#define BKT 16

static const long long QKV_ELEMS = 4LL * 4096 * 768;
static const long long S_ELEMS   = 4LL * 4096 * 4096;
static const long long H_ELEMS   = 16384LL * 3072;

__device__ float g_Q[4LL * 4096 * 768];
__device__ float g_K[4LL * 4096 * 768];
__device__ float g_V[4LL * 4096 * 768];
__device__ float g_S[4LL * 4096 * 4096];
__device__ float g_H[16384LL * 3072];

// C[M,N] = A[M,K] * op(B) (+bias)(+relu)
//   BT=true : B is [N,K] row-major (K-major, i.e. C = A @ B^T)
//   BT=false: B is [K,N] row-major (N-major, i.e. C = A @ B)
// blockIdx.z batches with the given element strides.
template <bool BT, bool RELU, bool BIAS>
__global__ __launch_bounds__(256)
void gemm_kernel(const float* __restrict__ A, const float* __restrict__ B,
                 const float* __restrict__ bias, float* __restrict__ C,
                 const int M, const int N, const int K,
                 const long long bA, const long long bB, const long long bC)
{
    __shared__ float As[BKT][BMT + 4];
    __shared__ float Bs[BKT][BNT + 4];

    const int tid = threadIdx.x;
    const int bm = blockIdx.y * BMT;
    const int bn = blockIdx.x * BNT;

    const float* Ab = A + (long long)blockIdx.z * bA + (long long)bm * K;
    const float* Bb;
    if (BT) Bb = B + (long long)blockIdx.z * bB + (long long)bn * K;
    else    Bb = B + (long long)blockIdx.z * bB + bn;
    float* Cb = C + (long long)blockIdx.z * bC;

    const int tx = tid & 15;          // 0..15 -> n
    const int ty = tid >> 4;          // 0..15 -> m
    const int m0 = ty * 8;
    const int n0 = tx * 8;

    // K-major tile loads (A always; B when BT): 128 rows x 16 cols
    const int lr = tid >> 2;          // 0..63
    const int lc = (tid & 3) * 4;     // 0,4,8,12
    // N-major B tile loads (when !BT): 16 rows x 128 cols
    const int lk = tid >> 5;          // 0..7
    const int ln = (tid & 31) * 4;    // 0..124

    float4 pa0, pa1, pb0, pb1;
    float acc[8][8];
#pragma unroll
    for (int i = 0; i < 8; ++i)
#pragma unroll
        for (int j = 0; j < 8; ++j) acc[i][j] = 0.0f;

#define LD_TILES(kt) do {                                                        \
        const float* _pa = Ab + (long long)lr * K + (kt) * BKT + lc;             \
        pa0 = *(const float4*)_pa;                                               \
        pa1 = *(const float4*)(_pa + 64LL * K);                                  \
        if (BT) {                                                                \
            const float* _pb = Bb + (long long)lr * K + (kt) * BKT + lc;         \
            pb0 = *(const float4*)_pb;                                           \
            pb1 = *(const float4*)(_pb + 64LL * K);                              \
        } else {                                                                 \
            const float* _pb = Bb + (long long)((kt) * BKT + lk) * N + ln;       \
            pb0 = *(const float4*)_pb;                                           \
            pb1 = *(const float4*)(_pb + 8LL * N);                               \
        }                                                                        \
    } while (0)

#define ST_TILES() do {                                                          \
        As[lc + 0][lr] = pa0.x; As[lc + 1][lr] = pa0.y;                          \
        As[lc + 2][lr] = pa0.z; As[lc + 3][lr] = pa0.w;                          \
        As[lc + 0][lr + 64] = pa1.x; As[lc + 1][lr + 64] = pa1.y;                \
        As[lc + 2][lr + 64] = pa1.z; As[lc + 3][lr + 64] = pa1.w;                \
        if (BT) {                                                                \
            Bs[lc + 0][lr] = pb0.x; Bs[lc + 1][lr] = pb0.y;                      \
            Bs[lc + 2][lr] = pb0.z; Bs[lc + 3][lr] = pb0.w;                      \
            Bs[lc + 0][lr + 64] = pb1.x; Bs[lc + 1][lr + 64] = pb1.y;            \
            Bs[lc + 2][lr + 64] = pb1.z; Bs[lc + 3][lr + 64] = pb1.w;            \
        } else {                                                                 \
            *(float4*)&Bs[lk][ln]     = pb0;                                     \
            *(float4*)&Bs[lk + 8][ln] = pb1;                                     \
        }                                                                        \
    } while (0)

    const int KT = K / BKT;
    LD_TILES(0);
    ST_TILES();
    __syncthreads();

    for (int kt = 1; kt <= KT; ++kt) {
        const bool more = (kt < KT);
        if (more) LD_TILES(kt);

#pragma unroll
        for (int kk = 0; kk < BKT; ++kk) {
            float ar[8], br[8];
            *(float4*)(ar)     = *(const float4*)&As[kk][m0];
            *(float4*)(ar + 4) = *(const float4*)&As[kk][m0 + 4];
            *(float4*)(br)     = *(const float4*)&Bs[kk][n0];
            *(float4*)(br + 4) = *(const float4*)&Bs[kk][n0 + 4];
#pragma unroll
            for (int i = 0; i < 8; ++i)
#pragma unroll
                for (int j = 0; j < 8; ++j)
                    acc[i][j] += ar[i] * br[j];
        }
        __syncthreads();
        if (more) {
            ST_TILES();
            __syncthreads();
        }
    }
#undef LD_TILES
#undef ST_TILES

    float4 bb0, bb1;
    if (BIAS) {
        bb0 = *(const float4*)&bias[bn + n0];
        bb1 = *(const float4*)&bias[bn + n0 + 4];
    }
#pragma unroll
    for (int i = 0; i < 8; ++i) {
        float4 v0, v1;
        v0.x = acc[i][0]; v0.y = acc[i][1]; v0.z = acc[i][2]; v0.w = acc[i][3];
        v1.x = acc[i][4]; v1.y = acc[i][5]; v1.z = acc[i][6]; v1.w = acc[i][7];
        if (BIAS) {
            v0.x += bb0.x; v0.y += bb0.y; v0.z += bb0.z; v0.w += bb0.w;
            v1.x += bb1.x; v1.y += bb1.y; v1.z += bb1.z; v1.w += bb1.w;
        }
        if (RELU) {
            v0.x = fmaxf(v0.x, 0.f); v0.y = fmaxf(v0.y, 0.f);
            v0.z = fmaxf(v0.z, 0.f); v0.w = fmaxf(v0.w, 0.f);
            v1.x = fmaxf(v1.x, 0.f); v1.y = fmaxf(v1.y, 0.f);
            v1.z = fmaxf(v1.z, 0.f); v1.w = fmaxf(v1.w, 0.f);
        }
        float* cp = Cb + (long long)(bm + m0 + i) * N + bn + n0;
        *(float4*)cp       = v0;
        *(float4*)(cp + 4) = v1;
    }
}

// In-place softmax over rows of length 4096; one block (256 threads) per row.
__global__ __launch_bounds__(256)
void softmax_kernel(float* __restrict__ S)
{
    __shared__ float red[8];
    const long long row = blockIdx.x;
    float* p = S + row * 4096;
    const int tid  = threadIdx.x;
    const int lane = tid & 31;
    const int warp = tid >> 5;

    float4 v[4];
#pragma unroll
    for (int i = 0; i < 4; ++i)
        v[i] = *(const float4*)(p + tid * 4 + i * 1024);

    float mx = -3.402823466e38f;
#pragma unroll
    for (int i = 0; i < 4; ++i) {
        mx = fmaxf(mx, fmaxf(fmaxf(v[i].x, v[i].y), fmaxf(v[i].z, v[i].w)));
    }
#pragma unroll
    for (int o = 16; o > 0; o >>= 1)
        mx = fmaxf(mx, __shfl_xor_sync(0xffffffffu, mx, o));
    if (lane == 0) red[warp] = mx;
    __syncthreads();
    float rowmax = red[0];
#pragma unroll
    for (int w = 1; w < 8; ++w) rowmax = fmaxf(rowmax, red[w]);
    __syncthreads();

    float sum = 0.0f;
#pragma unroll
    for (int i = 0; i < 4; ++i) {
        v[i].x = __expf(v[i].x - rowmax);
        v[i].y = __expf(v[i].y - rowmax);
        v[i].z = __expf(v[i].z - rowmax);
        v[i].w = __expf(v[i].w - rowmax);
        sum += (v[i].x + v[i].y) + (v[i].z + v[i].w);
    }
#pragma unroll
    for (int o = 16; o > 0; o >>= 1)
        sum += __shfl_xor_sync(0xffffffffu, sum, o);
    if (lane == 0) red[warp] = sum;
    __syncthreads();
    float rowsum = 0.0f;
#pragma unroll
    for (int w = 0; w < 8; ++w) rowsum += red[w];
    const float inv = 1.0f / rowsum;

#pragma unroll
    for (int i = 0; i < 4; ++i) {
        v[i].x *= inv; v[i].y *= inv; v[i].z *= inv; v[i].w *= inv;
        *(float4*)(p + tid * 4 + i * 1024) = v[i];
    }
}

extern "C" void kernel_launch(void* const* d_in, const int* in_sizes, int n_in,
                              void* d_out, int out_size)
{
    const float* X  = (const float*)d_in[0];
    const float* Wq = (const float*)d_in[1];
    const float* Wk = (const float*)d_in[2];
    const float* Wv = (const float*)d_in[3];
    const float* W1 = (const float*)d_in[4];
    const float* b1 = (const float*)d_in[5];
    const float* W2 = (const float*)d_in[6];
    const float* b2 = (const float*)d_in[7];
    float* out = (float*)d_out;

    float *Q, *Kb, *V, *S, *H;
    cudaGetSymbolAddress((void**)&Q,  g_Q);
    cudaGetSymbolAddress((void**)&Kb, g_K);
    cudaGetSymbolAddress((void**)&V,  g_V);
    cudaGetSymbolAddress((void**)&S,  g_S);
    cudaGetSymbolAddress((void**)&H,  g_H);

    const dim3 blk(256);

    // QKV projections: [16384,768] @ [768,768]^T
    gemm_kernel<true, false, false><<<dim3(6, 128, 1), blk>>>(
        X, Wq, nullptr, Q, 16384, 768, 768, 0, 0, 0);
    gemm_kernel<true, false, false><<<dim3(6, 128, 1), blk>>>(
        X, Wk, nullptr, Kb, 16384, 768, 768, 0, 0, 0);
    gemm_kernel<true, false, false><<<dim3(6, 128, 1), blk>>>(
        X, Wv, nullptr, V, 16384, 768, 768, 0, 0, 0);

    // scores = Q @ K^T per batch: [4096,768] @ [4096,768]^T
    gemm_kernel<true, false, false><<<dim3(32, 32, 4), blk>>>(
        Q, Kb, nullptr, S, 4096, 4096, 768,
        4096LL * 768, 4096LL * 768, 4096LL * 4096);

    // softmax over 16384 rows of 4096
    softmax_kernel<<<16384, blk>>>(S);

    // newV = attn @ V per batch: [4096,4096] @ [4096,768]  (reuse Q buffer)
    gemm_kernel<false, false, false><<<dim3(6, 32, 4), blk>>>(
        S, V, nullptr, Q, 4096, 768, 4096,
        4096LL * 4096, 4096LL * 768, 4096LL * 768);

    // h = relu(newV @ W1^T + b1): [16384,768] @ [3072,768]^T
    gemm_kernel<true, true, true><<<dim3(24, 128, 1), blk>>>(
        Q, W1, b1, H, 16384, 3072, 768, 0, 0, 0);

    // out = h @ W2^T + b2: [16384,3072] @ [768,3072]^T
    gemm_kernel<true, false, true><<<dim3(6, 128, 1), blk>>>(
        H, W2, b2, out, 16384, 768, 3072, 0, 0, 0);
}

// round 3
// speedup vs baseline: 1.7599x; 1.7599x over previous
#include <cuda_runtime.h>
#include <cuda_bf16.h>
#include <stdint.h>

// ============================================================================
// GPT block via warp-level mma.sync (bf16x3 split precision), sm_100-safe.
// Every GEMM: C = A @ B^T, A[M,K] & B[N,K] row-major bf16 (hi,lo) pairs.
// D = Ahi*Bhi + Ahi*Blo + Alo*Bhi accumulated in fp32 registers.
// ============================================================================

typedef __nv_bfloat16 bf16;

// ---------------- small helpers ----------------
__device__ __forceinline__ uint32_t smem_u32(const void* p) {
    uint32_t a;
    asm("{ .reg .u64 t; cvta.to.shared.u64 t, %1; cvt.u32.u64 %0, t; }"
        : "=r"(a) : "l"(p));
    return a;
}
__device__ __forceinline__ void cp16(uint32_t saddr, const void* g) {
    asm volatile("cp.async.cg.shared.global [%0], [%1], 16;"
                 :: "r"(saddr), "l"(g) : "memory");
}
#define CP_COMMIT() asm volatile("cp.async.commit_group;" ::: "memory")
#define CP_WAIT1()  asm volatile("cp.async.wait_group 1;" ::: "memory")

__device__ __forceinline__ void ldsm4(uint32_t* r, uint32_t a) {
    asm volatile("ldmatrix.sync.aligned.m8n8.x4.shared.b16 {%0,%1,%2,%3}, [%4];"
                 : "=r"(r[0]), "=r"(r[1]), "=r"(r[2]), "=r"(r[3]) : "r"(a));
}
__device__ __forceinline__ void mma16816(float* c, const uint32_t* a,
                                         const uint32_t* b) {
    asm volatile(
        "mma.sync.aligned.m16n8k16.row.col.f32.bf16.bf16.f32 "
        "{%0,%1,%2,%3}, {%4,%5,%6,%7}, {%8,%9}, {%0,%1,%2,%3};"
        : "+f"(c[0]), "+f"(c[1]), "+f"(c[2]), "+f"(c[3])
        : "r"(a[0]), "r"(a[1]), "r"(a[2]), "r"(a[3]), "r"(b[0]), "r"(b[1]));
}

// XOR swizzle: 16B chunk at (row, seg) of a [128 x 32bf16] tile (64B rows).
// Conflict-free for 8-lane ldmatrix phases and cp.async store phases.
__device__ __forceinline__ uint32_t swz(int r, int s) {
    return (uint32_t)(r * 64 + ((s ^ ((r >> 1) & 3)) << 4));
}

__device__ __forceinline__ void split2(float v, bf16& h, bf16& l) {
    h = __float2bfloat16(v);
    l = __float2bfloat16(v - __bfloat162float(h));
}

// ---------------- scratch ----------------
__device__ bf16 g_Xhi[16384LL * 768], g_Xlo[16384LL * 768];
__device__ bf16 g_Wqhi[768 * 768], g_Wqlo[768 * 768];
__device__ bf16 g_Wkhi[768 * 768], g_Wklo[768 * 768];
__device__ bf16 g_Wvhi[768 * 768], g_Wvlo[768 * 768];
__device__ bf16 g_W1hi[3072 * 768], g_W1lo[3072 * 768];
__device__ bf16 g_W2hi[768 * 3072], g_W2lo[768 * 3072];
__device__ bf16 g_Qhi[4LL * 4096 * 768], g_Qlo[4LL * 4096 * 768];
__device__ bf16 g_Khi[4LL * 4096 * 768], g_Klo[4LL * 4096 * 768];
__device__ float g_Vf[4LL * 4096 * 768];
__device__ bf16 g_VThi[4LL * 768 * 4096], g_VTlo[4LL * 768 * 4096];
__device__ float g_S[4LL * 4096 * 4096];
__device__ bf16 g_Phi[4LL * 4096 * 4096], g_Plo[4LL * 4096 * 4096];
__device__ bf16 g_NVhi[4LL * 4096 * 768], g_NVlo[4LL * 4096 * 768];
__device__ bf16 g_Hhi[16384LL * 3072], g_Hlo[16384LL * 3072];

// ---------------- GEMM ----------------
// stage layout: Ahi@0, Alo@8192, Bhi@16384, Blo@24576 ; stage stride 32768
static constexpr int STAGE_BYTES = 32768;
static constexpr int SMEM_TOTAL  = 3 * STAGE_BYTES;

__device__ __forceinline__ void load_stage(
    uint32_t so, int tid,
    const bf16* __restrict__ Ah, const bf16* __restrict__ Al,
    const bf16* __restrict__ Bh, const bf16* __restrict__ Bl,
    long long k0, int K)
{
    const int r = tid & 127, h = tid >> 7;
    const long long ga = (long long)r * K + k0 + h * 16;
#pragma unroll
    for (int u = 0; u < 2; ++u) {
        const uint32_t d = swz(r, h * 2 + u);
        const long long g = ga + u * 8;
        cp16(so + d,         Ah + g);
        cp16(so + 8192 + d,  Al + g);
        cp16(so + 16384 + d, Bh + g);
        cp16(so + 24576 + d, Bl + g);
    }
}

template <bool BIAS, bool RELU, bool PAIR>
__global__ __launch_bounds__(256, 1)
void wm_gemm(const bf16* __restrict__ Ahi, const bf16* __restrict__ Alo,
             const bf16* __restrict__ Bhi, const bf16* __restrict__ Blo,
             const float* __restrict__ bias,
             float* __restrict__ Cf, bf16* __restrict__ Chi, bf16* __restrict__ Clo,
             const int N, const int K,
             const long long bA, const long long bB, const long long bC)
{
    extern __shared__ __align__(128) char smem[];
    const uint32_t sb = smem_u32(smem);
    const int tid = threadIdx.x;
    const int wid = tid >> 5, lane = tid & 31;
    const int wm = wid >> 1, wn = wid & 1;
    const int lj = lane >> 3, lr = lane & 7;

    const long long bm = (long long)blockIdx.y * 128;
    const long long bn = (long long)blockIdx.x * 128;

    const bf16* Ah = Ahi + (long long)blockIdx.z * bA + bm * K;
    const bf16* Al = Alo + (long long)blockIdx.z * bA + bm * K;
    const bf16* Bh = Bhi + (long long)blockIdx.z * bB + bn * K;
    const bf16* Bl = Blo + (long long)blockIdx.z * bB + bn * K;

    float acc[2][8][4];
#pragma unroll
    for (int i = 0; i < 2; ++i)
#pragma unroll
        for (int j = 0; j < 8; ++j)
#pragma unroll
            for (int t = 0; t < 4; ++t) acc[i][j][t] = 0.0f;

    const int NC = K / 32;

    load_stage(sb, tid, Ah, Al, Bh, Bl, 0, K);
    CP_COMMIT();
    load_stage(sb + STAGE_BYTES, tid, Ah, Al, Bh, Bl, 32, K);
    CP_COMMIT();

    int buf = 0;
    for (int c = 0; c < NC; ++c) {
        CP_WAIT1();
        __syncthreads();
        if (c + 2 < NC) {
            int nb = buf + 2; if (nb >= 3) nb -= 3;
            load_stage(sb + nb * STAGE_BYTES, tid, Ah, Al, Bh, Bl,
                       (long long)(c + 2) * 32, K);
        }
        CP_COMMIT();

        const uint32_t bb = sb + buf * STAGE_BYTES;
#pragma unroll
        for (int ks = 0; ks < 2; ++ks) {
            uint32_t Afh[2][4], Afl[2][4];
#pragma unroll
            for (int mt = 0; mt < 2; ++mt) {
                const int row = wm * 32 + mt * 16 + ((lj & 1) << 3) + lr;
                const int seg = ks * 2 + (lj >> 1);
                const uint32_t off = swz(row, seg);
                ldsm4(Afh[mt], bb + off);
                ldsm4(Afl[mt], bb + 8192 + off);
            }
            uint32_t Bfh[4][4], Bfl[4][4];
#pragma unroll
            for (int ntp = 0; ntp < 4; ++ntp) {
                const int row = wn * 64 + ntp * 16 + ((lj >> 1) << 3) + lr;
                const int seg = ks * 2 + (lj & 1);
                const uint32_t off = swz(row, seg);
                ldsm4(Bfh[ntp], bb + 16384 + off);
                ldsm4(Bfl[ntp], bb + 24576 + off);
            }
#pragma unroll
            for (int mt = 0; mt < 2; ++mt)
#pragma unroll
                for (int nt = 0; nt < 8; ++nt) {
                    float* cc = acc[mt][nt];
                    const uint32_t* bhp = &Bfh[nt >> 1][(nt & 1) * 2];
                    const uint32_t* blp = &Bfl[nt >> 1][(nt & 1) * 2];
                    mma16816(cc, Afh[mt], bhp);
                    mma16816(cc, Afh[mt], blp);
                    mma16816(cc, Afl[mt], bhp);
                }
        }
        ++buf; if (buf == 3) buf = 0;
    }

    // ---- epilogue ----
    const long long zC = (long long)blockIdx.z * bC;
    const int rbase = (int)bm + wm * 32 + (lane >> 2);
    const int cbase = (int)bn + wn * 64 + (lane & 3) * 2;

#pragma unroll
    for (int mt = 0; mt < 2; ++mt)
#pragma unroll
        for (int nt = 0; nt < 8; ++nt) {
            const int col = cbase + nt * 8;
            float b0 = 0.f, b1 = 0.f;
            if (BIAS) { b0 = bias[col]; b1 = bias[col + 1]; }
#pragma unroll
            for (int rh = 0; rh < 2; ++rh) {
                const int row = rbase + mt * 16 + rh * 8;
                float v0 = acc[mt][nt][rh * 2 + 0];
                float v1 = acc[mt][nt][rh * 2 + 1];
                if (BIAS) { v0 += b0; v1 += b1; }
                if (RELU) { v0 = fmaxf(v0, 0.f); v1 = fmaxf(v1, 0.f); }
                const long long o = zC + (long long)row * N + col;
                if (PAIR) {
                    bf16 h0, l0, h1, l1;
                    split2(v0, h0, l0);
                    split2(v1, h1, l1);
                    __nv_bfloat162 hp; hp.x = h0; hp.y = h1;
                    __nv_bfloat162 lp; lp.x = l0; lp.y = l1;
                    *(__nv_bfloat162*)(Chi + o) = hp;
                    *(__nv_bfloat162*)(Clo + o) = lp;
                } else {
                    float2 w; w.x = v0; w.y = v1;
                    *(float2*)(Cf + o) = w;
                }
            }
        }
}

// ---------------- fp32 -> (hi,lo) bf16 elementwise ----------------
__global__ __launch_bounds__(256)
void cvt_pair(const float* __restrict__ in, bf16* __restrict__ hi,
              bf16* __restrict__ lo, const long long n)
{
    const long long i = ((long long)blockIdx.x * 256 + threadIdx.x) * 4;
    if (i >= n) return;
    const float4 v = *(const float4*)(in + i);
    __align__(8) bf16 h[4];
    __align__(8) bf16 l[4];
    split2(v.x, h[0], l[0]); split2(v.y, h[1], l[1]);
    split2(v.z, h[2], l[2]); split2(v.w, h[3], l[3]);
    *(uint2*)(hi + i) = *(const uint2*)h;
    *(uint2*)(lo + i) = *(const uint2*)l;
}

// ---------------- V transpose+split: [b,4096,768]f32 -> [b,768,4096] pair ----
__global__ __launch_bounds__(256)
void transpose_cvt(const float* __restrict__ V, bf16* __restrict__ Thi,
                   bf16* __restrict__ Tlo)
{
    __shared__ float tile[32][33];
    const int b = blockIdx.z;
    const int e0 = blockIdx.x * 32;
    const int t0 = blockIdx.y * 32;
    const float* Vb = V + (long long)b * 4096 * 768;
    bf16* Hb = Thi + (long long)b * 768 * 4096;
    bf16* Lb = Tlo + (long long)b * 768 * 4096;
    const int tx = threadIdx.x, ty = threadIdx.y;
#pragma unroll
    for (int j = 0; j < 32; j += 8)
        tile[ty + j][tx] = Vb[(long long)(t0 + ty + j) * 768 + e0 + tx];
    __syncthreads();
#pragma unroll
    for (int j = 0; j < 32; j += 8) {
        bf16 h, l;
        split2(tile[tx][ty + j], h, l);
        const long long o = (long long)(e0 + ty + j) * 4096 + t0 + tx;
        Hb[o] = h;
        Lb[o] = l;
    }
}

// ---------------- softmax (rows of 4096) -> (hi,lo) bf16 ----------------
__global__ __launch_bounds__(256)
void softmax_pair(const float* __restrict__ S, bf16* __restrict__ Phi,
                  bf16* __restrict__ Plo)
{
    __shared__ float red[8];
    const long long row = blockIdx.x;
    const float* p = S + row * 4096;
    const int tid = threadIdx.x, lane = tid & 31, warp = tid >> 5;

    float4 v[4];
#pragma unroll
    for (int i = 0; i < 4; ++i)
        v[i] = *(const float4*)(p + tid * 4 + i * 1024);

    float mx = -3.402823466e38f;
#pragma unroll
    for (int i = 0; i < 4; ++i)
        mx = fmaxf(mx, fmaxf(fmaxf(v[i].x, v[i].y), fmaxf(v[i].z, v[i].w)));
#pragma unroll
    for (int o = 16; o > 0; o >>= 1)
        mx = fmaxf(mx, __shfl_xor_sync(0xffffffffu, mx, o));
    if (lane == 0) red[warp] = mx;
    __syncthreads();
    float rowmax = red[0];
#pragma unroll
    for (int w = 1; w < 8; ++w) rowmax = fmaxf(rowmax, red[w]);
    __syncthreads();

    float sum = 0.0f;
#pragma unroll
    for (int i = 0; i < 4; ++i) {
        v[i].x = __expf(v[i].x - rowmax);
        v[i].y = __expf(v[i].y - rowmax);
        v[i].z = __expf(v[i].z - rowmax);
        v[i].w = __expf(v[i].w - rowmax);
        sum += (v[i].x + v[i].y) + (v[i].z + v[i].w);
    }
#pragma unroll
    for (int o = 16; o > 0; o >>= 1)
        sum += __shfl_xor_sync(0xffffffffu, sum, o);
    if (lane == 0) red[warp] = sum;
    __syncthreads();
    float rowsum = 0.0f;
#pragma unroll
    for (int w = 0; w < 8; ++w) rowsum += red[w];
    const float inv = 1.0f / rowsum;

#pragma unroll
    for (int i = 0; i < 4; ++i) {
        __align__(8) bf16 h[4];
        __align__(8) bf16 l[4];
        split2(v[i].x * inv, h[0], l[0]);
        split2(v[i].y * inv, h[1], l[1]);
        split2(v[i].z * inv, h[2], l[2]);
        split2(v[i].w * inv, h[3], l[3]);
        const long long o = row * 4096 + tid * 4 + i * 1024;
        *(uint2*)(Phi + o) = *(const uint2*)h;
        *(uint2*)(Plo + o) = *(const uint2*)l;
    }
}

// ---------------- host ----------------
extern "C" void kernel_launch(void* const* d_in, const int* in_sizes, int n_in,
                              void* d_out, int out_size)
{
    const float* X  = (const float*)d_in[0];
    const float* Wq = (const float*)d_in[1];
    const float* Wk = (const float*)d_in[2];
    const float* Wv = (const float*)d_in[3];
    const float* W1 = (const float*)d_in[4];
    const float* b1 = (const float*)d_in[5];
    const float* W2 = (const float*)d_in[6];
    const float* b2 = (const float*)d_in[7];
    float* out = (float*)d_out;

    bf16 *Xhi, *Xlo, *Wqhi, *Wqlo, *Wkhi, *Wklo, *Wvhi, *Wvlo;
    bf16 *W1hi, *W1lo, *W2hi, *W2lo;
    bf16 *Qhi, *Qlo, *Khi, *Klo, *VThi, *VTlo, *Phi, *Plo, *NVhi, *NVlo, *Hhi, *Hlo;
    float *Vf, *S;
    cudaGetSymbolAddress((void**)&Xhi, g_Xhi);   cudaGetSymbolAddress((void**)&Xlo, g_Xlo);
    cudaGetSymbolAddress((void**)&Wqhi, g_Wqhi); cudaGetSymbolAddress((void**)&Wqlo, g_Wqlo);
    cudaGetSymbolAddress((void**)&Wkhi, g_Wkhi); cudaGetSymbolAddress((void**)&Wklo, g_Wklo);
    cudaGetSymbolAddress((void**)&Wvhi, g_Wvhi); cudaGetSymbolAddress((void**)&Wvlo, g_Wvlo);
    cudaGetSymbolAddress((void**)&W1hi, g_W1hi); cudaGetSymbolAddress((void**)&W1lo, g_W1lo);
    cudaGetSymbolAddress((void**)&W2hi, g_W2hi); cudaGetSymbolAddress((void**)&W2lo, g_W2lo);
    cudaGetSymbolAddress((void**)&Qhi, g_Qhi);   cudaGetSymbolAddress((void**)&Qlo, g_Qlo);
    cudaGetSymbolAddress((void**)&Khi, g_Khi);   cudaGetSymbolAddress((void**)&Klo, g_Klo);
    cudaGetSymbolAddress((void**)&Vf, g_Vf);
    cudaGetSymbolAddress((void**)&VThi, g_VThi); cudaGetSymbolAddress((void**)&VTlo, g_VTlo);
    cudaGetSymbolAddress((void**)&S, g_S);
    cudaGetSymbolAddress((void**)&Phi, g_Phi);   cudaGetSymbolAddress((void**)&Plo, g_Plo);
    cudaGetSymbolAddress((void**)&NVhi, g_NVhi); cudaGetSymbolAddress((void**)&NVlo, g_NVlo);
    cudaGetSymbolAddress((void**)&Hhi, g_Hhi);   cudaGetSymbolAddress((void**)&Hlo, g_Hlo);

    cudaFuncSetAttribute(wm_gemm<false, false, true>,
                         cudaFuncAttributeMaxDynamicSharedMemorySize, SMEM_TOTAL);
    cudaFuncSetAttribute(wm_gemm<false, false, false>,
                         cudaFuncAttributeMaxDynamicSharedMemorySize, SMEM_TOTAL);
    cudaFuncSetAttribute(wm_gemm<true, true, true>,
                         cudaFuncAttributeMaxDynamicSharedMemorySize, SMEM_TOTAL);
    cudaFuncSetAttribute(wm_gemm<true, false, false>,
                         cudaFuncAttributeMaxDynamicSharedMemorySize, SMEM_TOTAL);

    // split inputs/weights
    cvt_pair<<<12288, 256>>>(X,  Xhi,  Xlo,  16384LL * 768);
    cvt_pair<<<576,  256>>>(Wq, Wqhi, Wqlo, 768LL * 768);
    cvt_pair<<<576,  256>>>(Wk, Wkhi, Wklo, 768LL * 768);
    cvt_pair<<<576,  256>>>(Wv, Wvhi, Wvlo, 768LL * 768);
    cvt_pair<<<2304, 256>>>(W1, W1hi, W1lo, 3072LL * 768);
    cvt_pair<<<2304, 256>>>(W2, W2hi, W2lo, 768LL * 3072);

    // Q = X @ Wq^T, K = X @ Wk^T (pair out); Vf = X @ Wv^T (fp32 out)
    wm_gemm<false, false, true><<<dim3(6, 128, 1), 256, SMEM_TOTAL>>>(
        Xhi, Xlo, Wqhi, Wqlo, nullptr, nullptr, Qhi, Qlo, 768, 768, 0, 0, 0);
    wm_gemm<false, false, true><<<dim3(6, 128, 1), 256, SMEM_TOTAL>>>(
        Xhi, Xlo, Wkhi, Wklo, nullptr, nullptr, Khi, Klo, 768, 768, 0, 0, 0);
    wm_gemm<false, false, false><<<dim3(6, 128, 1), 256, SMEM_TOTAL>>>(
        Xhi, Xlo, Wvhi, Wvlo, nullptr, Vf, nullptr, nullptr, 768, 768, 0, 0, 0);

    // V^T (pair) so attn@V is the same NT GEMM
    transpose_cvt<<<dim3(24, 128, 4), dim3(32, 8)>>>(Vf, VThi, VTlo);

    // scores = Q @ K^T per batch (fp32 out)
    wm_gemm<false, false, false><<<dim3(32, 32, 4), 256, SMEM_TOTAL>>>(
        Qhi, Qlo, Khi, Klo, nullptr, S, nullptr, nullptr, 4096, 768,
        4096LL * 768, 4096LL * 768, 4096LL * 4096);

    // softmax -> P (pair)
    softmax_pair<<<16384, 256>>>(S, Phi, Plo);

    // newV = P @ VT^T per batch (pair out)
    wm_gemm<false, false, true><<<dim3(6, 32, 4), 256, SMEM_TOTAL>>>(
        Phi, Plo, VThi, VTlo, nullptr, nullptr, NVhi, NVlo, 768, 4096,
        4096LL * 4096, 768LL * 4096, 4096LL * 768);

    // H = relu(newV @ W1^T + b1) (pair out)
    wm_gemm<true, true, true><<<dim3(24, 128, 1), 256, SMEM_TOTAL>>>(
        NVhi, NVlo, W1hi, W1lo, b1, nullptr, Hhi, Hlo, 3072, 768, 0, 0, 0);

    // out = H @ W2^T + b2 (fp32 out)
    wm_gemm<true, false, false><<<dim3(6, 128, 1), 256, SMEM_TOTAL>>>(
        Hhi, Hlo, W2hi, W2lo, b2, out, nullptr, nullptr, 768, 3072, 0, 0, 0);
}